// round 8
// baseline (speedup 1.0000x reference)
#include <cuda_runtime.h>
#include <cuda_bf16.h>
#include <math.h>

// ---------------- problem constants ----------------
#define DIMC    96
#define NHC     3
#define HEADC   32
#define WSC     7
#define SHIFTC  3
#define PC      5
#define HC      56
#define NWC     64
#define TPC     320
#define NNC     54
#define BATCHC  64
#define TOKC    3456
#define MROWS   (BATCHC * NWC * NNC)   // 221184
#define HIDC    384
#define SCALEC  0.17677669529663687f

// ---------------- scratch (split format: uint2{hi bf16 pair, lo bf16 pair}) ----------------
__device__ __align__(16) uint2 g_xw_sp   [MROWS * 48];            // LN1 out, window order
__device__ float               g_qkv     [(size_t)MROWS * 3 * DIMC];
__device__ __align__(16) uint2 g_attno_sp[MROWS * 48];            // attn out, window order
__device__ float               g_y       [MROWS * DIMC];          // residual stream (fp32)
__device__ __align__(16) uint2 g_yn_sp   [MROWS * 48];            // LN2 out
__device__ __align__(16) uint2 g_h_sp    [(size_t)MROWS * 192];   // fc1+GELU out
// pre-split weights [kpair][n]
__device__ __align__(16) uint2 g_wq_sp[48 * 288];
__device__ __align__(16) uint2 g_wp_sp[48 * 96];
__device__ __align__(16) uint2 g_w1_sp[48 * 384];
__device__ __align__(16) uint2 g_w2_sp[192 * 96];

__device__ __forceinline__ int map_token(int bw, int n) {
    int b = bw >> 6;
    int w = bw & 63;
    int tok;
    if (n < PC) {
        tok = w * PC + n;
    } else {
        int p  = n - PC;
        int r  = p / 7, c = p % 7;
        int wh = w >> 3, ww = w & 7;
        int hr = wh * 7 + r + SHIFTC; if (hr >= HC) hr -= HC;
        int wc = ww * 7 + c + SHIFTC; if (wc >= HC) wc -= HC;
        tok = TPC + hr * HC + wc;
    }
    return b * TOKC + tok;
}

__device__ __forceinline__ float warp_sum(float v) {
    #pragma unroll
    for (int o = 16; o; o >>= 1) v += __shfl_xor_sync(0xffffffffu, v, o);
    return v;
}

__device__ __forceinline__ uint2 split_bf16_pair(float x0, float x1) {
    __nv_bfloat16 h0 = __float2bfloat16(x0);
    __nv_bfloat16 h1 = __float2bfloat16(x1);
    float r0 = x0 - __bfloat162float(h0);
    float r1 = x1 - __bfloat162float(h1);
    __nv_bfloat16 l0 = __float2bfloat16(r0);
    __nv_bfloat16 l1 = __float2bfloat16(r1);
    uint2 o;
    o.x = ((unsigned)__bfloat16_as_ushort(h1) << 16) | (unsigned)__bfloat16_as_ushort(h0);
    o.y = ((unsigned)__bfloat16_as_ushort(l1) << 16) | (unsigned)__bfloat16_as_ushort(l0);
    return o;
}

// ---------------- weight pre-split ----------------
__global__ __launch_bounds__(256)
void split_w_kernel(const float* __restrict__ qkv_w, const float* __restrict__ proj_w,
                    const float* __restrict__ fc1_w, const float* __restrict__ fc2_w) {
    int i = blockIdx.x * blockDim.x + threadIdx.x;
    if (i < 13824) {
        int kp = i / 288, n = i % 288;
        g_wq_sp[i] = split_bf16_pair(qkv_w[(2 * kp) * 288 + n], qkv_w[(2 * kp + 1) * 288 + n]);
    } else if (i < 18432) {
        int j = i - 13824, kp = j / 96, n = j % 96;
        g_wp_sp[j] = split_bf16_pair(proj_w[(2 * kp) * 96 + n], proj_w[(2 * kp + 1) * 96 + n]);
    } else if (i < 36864) {
        int j = i - 18432, kp = j / 384, n = j % 384;
        g_w1_sp[j] = split_bf16_pair(fc1_w[(2 * kp) * 384 + n], fc1_w[(2 * kp + 1) * 384 + n]);
    } else if (i < 55296) {
        int j = i - 36864, kp = j / 96, n = j % 96;
        g_w2_sp[j] = split_bf16_pair(fc2_w[(2 * kp) * 96 + n], fc2_w[(2 * kp + 1) * 96 + n]);
    }
}

// ---------------- LN kernels (write split pairs) ----------------
__global__ __launch_bounds__(256)
void ln_gather_kernel(const float* __restrict__ x,
                      const float* __restrict__ g, const float* __restrict__ bta) {
    int row  = (blockIdx.x * blockDim.x + threadIdx.x) >> 5;
    int lane = threadIdx.x & 31;
    if (row >= MROWS) return;
    int bw = row / NNC, n = row % NNC;
    const float2* src2 = (const float2*)(x + (size_t)map_token(bw, n) * DIMC);
    float2 a0 = src2[lane];
    float2 a1 = make_float2(0.f, 0.f);
    if (lane < 16) a1 = src2[32 + lane];
    float s = a0.x + a0.y + a1.x + a1.y;
    float mean = warp_sum(s) * (1.f / 96.f);
    float d0x = a0.x - mean, d0y = a0.y - mean;
    float d1x = a1.x - mean, d1y = a1.y - mean;
    float vq = d0x * d0x + d0y * d0y + (lane < 16 ? d1x * d1x + d1y * d1y : 0.f);
    float var = warp_sum(vq) * (1.f / 96.f);
    float inv = rsqrtf(var + 1e-5f);
    const float2* g2 = (const float2*)g;
    const float2* b2 = (const float2*)bta;
    uint2* dst = g_xw_sp + (size_t)row * 48;
    float2 G = g2[lane], B = b2[lane];
    dst[lane] = split_bf16_pair(d0x * inv * G.x + B.x, d0y * inv * G.y + B.y);
    if (lane < 16) {
        float2 G1 = g2[32 + lane], B1 = b2[32 + lane];
        dst[32 + lane] = split_bf16_pair(d1x * inv * G1.x + B1.x, d1y * inv * G1.y + B1.y);
    }
}

__global__ __launch_bounds__(256)
void ln_plain_kernel(const float* __restrict__ y,
                     const float* __restrict__ g, const float* __restrict__ bta) {
    int row  = (blockIdx.x * blockDim.x + threadIdx.x) >> 5;
    int lane = threadIdx.x & 31;
    if (row >= MROWS) return;
    const float2* src2 = (const float2*)(y + (size_t)row * DIMC);
    float2 a0 = src2[lane];
    float2 a1 = make_float2(0.f, 0.f);
    if (lane < 16) a1 = src2[32 + lane];
    float s = a0.x + a0.y + a1.x + a1.y;
    float mean = warp_sum(s) * (1.f / 96.f);
    float d0x = a0.x - mean, d0y = a0.y - mean;
    float d1x = a1.x - mean, d1y = a1.y - mean;
    float vq = d0x * d0x + d0y * d0y + (lane < 16 ? d1x * d1x + d1y * d1y : 0.f);
    float var = warp_sum(vq) * (1.f / 96.f);
    float inv = rsqrtf(var + 1e-5f);
    const float2* g2 = (const float2*)g;
    const float2* b2 = (const float2*)bta;
    uint2* dst = g_yn_sp + (size_t)row * 48;
    float2 G = g2[lane], B = b2[lane];
    dst[lane] = split_bf16_pair(d0x * inv * G.x + B.x, d0y * inv * G.y + B.y);
    if (lane < 16) {
        float2 G1 = g2[32 + lane], B1 = b2[32 + lane];
        dst[32 + lane] = split_bf16_pair(d1x * inv * G1.x + B1.x, d1y * inv * G1.y + B1.y);
    }
}

// ---------------- BF16x3 tensor-core GEMM (unchanged) ----------------
__device__ __forceinline__ void mma16(float c[4],
                                      unsigned a0, unsigned a1, unsigned a2, unsigned a3,
                                      unsigned b0, unsigned b1) {
    asm volatile("mma.sync.aligned.m16n8k16.row.col.f32.bf16.bf16.f32 "
                 "{%0,%1,%2,%3}, {%4,%5,%6,%7}, {%8,%9}, {%0,%1,%2,%3};\n"
                 : "+f"(c[0]), "+f"(c[1]), "+f"(c[2]), "+f"(c[3])
                 : "r"(a0), "r"(a1), "r"(a2), "r"(a3), "r"(b0), "r"(b1));
}

#define GEMM_SMEM ((2 * 16 * 132 + 2 * 16 * 100) * 8)   // 59392 bytes

template<int MODE>
__global__ __launch_bounds__(256, 2)
void gemm_tc(const uint2* __restrict__ A, const uint2* __restrict__ Bw,
             const float* __restrict__ bias, const float* __restrict__ res,
             float* __restrict__ out, uint2* __restrict__ outp, int N, int K) {
    extern __shared__ uint2 smemu[];
    uint2 (*As2)[16][132] = reinterpret_cast<uint2(*)[16][132]>(smemu);
    uint2 (*Bs2)[16][100] = reinterpret_cast<uint2(*)[16][100]>(smemu + 2 * 16 * 132);

    const int tid  = threadIdx.x;
    const int wid  = tid >> 5, lane = tid & 31;
    const int gid  = lane >> 2, tig = lane & 3;
    const int wm   = (wid >> 1) * 32;
    const int wn   = (wid & 1) * 48;
    const int m0   = blockIdx.y * 128;
    const int n0   = blockIdx.x * 96;
    const int KP   = K >> 1;

    int arow[4], akp[4];
    const uint2* aPtr[4];
    #pragma unroll
    for (int j = 0; j < 4; j++) {
        int c = tid + 256 * j;
        arow[j] = c >> 3;
        akp[j]  = (c & 7) * 2;
        aPtr[j] = A + (size_t)(m0 + arow[j]) * KP + akp[j];
    }
    int bkp[3], bn2[3];
    const uint2* bPtr[3];
    #pragma unroll
    for (int j = 0; j < 3; j++) {
        int c = tid + 256 * j;
        bkp[j] = c / 48;
        bn2[j] = (c % 48) * 2;
        bPtr[j] = Bw + (size_t)bkp[j] * N + n0 + bn2[j];
    }

    float acc[2][6][4];
    #pragma unroll
    for (int i = 0; i < 2; i++)
        #pragma unroll
        for (int j = 0; j < 6; j++)
            #pragma unroll
            for (int r = 0; r < 4; r++) acc[i][j][r] = 0.f;

    uint4 aR[4], bR[3];
    #pragma unroll
    for (int j = 0; j < 4; j++) aR[j] = *(const uint4*)(aPtr[j]);
    #pragma unroll
    for (int j = 0; j < 3; j++) bR[j] = *(const uint4*)(bPtr[j]);

    #pragma unroll
    for (int j = 0; j < 4; j++) {
        As2[0][akp[j]][arow[j]]     = make_uint2(aR[j].x, aR[j].y);
        As2[0][akp[j] + 1][arow[j]] = make_uint2(aR[j].z, aR[j].w);
    }
    #pragma unroll
    for (int j = 0; j < 3; j++)
        *(uint4*)&Bs2[0][bkp[j]][bn2[j]] = bR[j];
    __syncthreads();

    const int T = K >> 5;
    for (int t = 0; t < T; t++) {
        const int s = t & 1;
        if (t + 1 < T) {
            const int kt = 16 * (t + 1);
            #pragma unroll
            for (int j = 0; j < 4; j++) aR[j] = *(const uint4*)(aPtr[j] + kt);
            #pragma unroll
            for (int j = 0; j < 3; j++) bR[j] = *(const uint4*)(bPtr[j] + (size_t)kt * N);
        }

        #pragma unroll
        for (int ks = 0; ks < 2; ks++) {
            const int kb = ks * 8;
            uint2 af[2][4];
            #pragma unroll
            for (int mt = 0; mt < 2; mt++) {
                const int m = wm + mt * 16 + gid;
                af[mt][0] = As2[s][kb + tig    ][m];
                af[mt][1] = As2[s][kb + tig    ][m + 8];
                af[mt][2] = As2[s][kb + tig + 4][m];
                af[mt][3] = As2[s][kb + tig + 4][m + 8];
            }
            uint2 bf[6][2];
            #pragma unroll
            for (int nt = 0; nt < 6; nt++) {
                const int n = wn + nt * 8 + gid;
                bf[nt][0] = Bs2[s][kb + tig    ][n];
                bf[nt][1] = Bs2[s][kb + tig + 4][n];
            }
            #pragma unroll
            for (int mt = 0; mt < 2; mt++)
                #pragma unroll
                for (int nt = 0; nt < 6; nt++) {
                    float* c = acc[mt][nt];
                    mma16(c, af[mt][0].x, af[mt][1].x, af[mt][2].x, af[mt][3].x,
                             bf[nt][0].x, bf[nt][1].x);
                    mma16(c, af[mt][0].x, af[mt][1].x, af[mt][2].x, af[mt][3].x,
                             bf[nt][0].y, bf[nt][1].y);
                    mma16(c, af[mt][0].y, af[mt][1].y, af[mt][2].y, af[mt][3].y,
                             bf[nt][0].x, bf[nt][1].x);
                }
        }

        if (t + 1 < T) {
            const int sn = (t + 1) & 1;
            #pragma unroll
            for (int j = 0; j < 4; j++) {
                As2[sn][akp[j]][arow[j]]     = make_uint2(aR[j].x, aR[j].y);
                As2[sn][akp[j] + 1][arow[j]] = make_uint2(aR[j].z, aR[j].w);
            }
            #pragma unroll
            for (int j = 0; j < 3; j++)
                *(uint4*)&Bs2[sn][bkp[j]][bn2[j]] = bR[j];
        }
        __syncthreads();
    }

    float bb[6][2];
    #pragma unroll
    for (int nt = 0; nt < 6; nt++) {
        int c = n0 + wn + nt * 8 + tig * 2;
        bb[nt][0] = bias[c];
        bb[nt][1] = bias[c + 1];
    }

    #pragma unroll
    for (int mt = 0; mt < 2; mt++) {
        #pragma unroll
        for (int half = 0; half < 2; half++) {
            int r = m0 + wm + mt * 16 + gid + half * 8;
            size_t orow;
            if (MODE == 1) orow = (size_t)map_token(r / NNC, r % NNC);
            else           orow = (size_t)r;
            #pragma unroll
            for (int nt = 0; nt < 6; nt++) {
                float v0 = acc[mt][nt][half * 2 + 0] + bb[nt][0];
                float v1 = acc[mt][nt][half * 2 + 1] + bb[nt][1];
                if (MODE == 2) {
                    v0 = 0.5f * v0 * (1.0f + erff(v0 * 0.70710678118654752f));
                    v1 = 0.5f * v1 * (1.0f + erff(v1 * 0.70710678118654752f));
                    uint2* op2 = outp + orow * (size_t)(N >> 1) + ((n0 + wn) >> 1) + tig;
                    op2[nt * 4] = split_bf16_pair(v0, v1);
                } else {
                    float* op = out + orow * N + n0 + wn + tig * 2 + nt * 8;
                    if (MODE == 1 || MODE == 3) {
                        const float* rp = res + orow * N + n0 + wn + tig * 2 + nt * 8;
                        v0 += rp[0];
                        v1 += rp[1];
                    }
                    *(float2*)op = make_float2(v0, v1);
                }
            }
        }
    }
}

// ---------------- MMA windowed attention (fixed Ss stride) ----------------
// One block per (window, head), 64 threads (2 warps). S = Q@K^T and O = P@V on
// tensor cores with bf16 hi/lo x3 split (same fragment scheme as gemm_tc).
// smem: Q[16][68] | K[16][68] (aliased later by P[32][68]), V[32][36],
//       S[64][65] fp32 (65 = odd stride, holds all 64 columns), tables.
__global__ __launch_bounds__(64)
void attn_kernel(const float* __restrict__ qkv, const float* __restrict__ rpb) {
    __shared__ __align__(16) uint2 QKbuf[32 * 68];      // 17408 B (Q 16x68 | K 16x68; later P 32x68)
    __shared__ __align__(16) uint2 Vs[32][36];          // 9216 B
    __shared__ float Ss[64][65];                        // 16640 B
    __shared__ float bt[169];
    __shared__ unsigned char fidx_s[49];
    __shared__ int regn_s[NNC];

    uint2 (*Qs)[68] = reinterpret_cast<uint2(*)[68]>(QKbuf);
    uint2 (*Ks)[68] = reinterpret_cast<uint2(*)[68]>(QKbuf + 16 * 68);
    uint2 (*Ps)[68] = reinterpret_cast<uint2(*)[68]>(QKbuf);

    const int bw   = blockIdx.x;
    const int head = blockIdx.y;
    const int base = bw * NNC;
    const int tid  = threadIdx.x;
    const int wid  = tid >> 5, lane = tid & 31;
    const int gid  = lane >> 2, tig = lane & 3;

    // ---- stage Q (scaled) and K as split pairs, [kpair][row] ----
    for (int idx = tid; idx < 64 * 16; idx += 64) {
        int r = idx >> 4, kp = idx & 15;
        if (r < NNC) {
            const float2* qp = (const float2*)(qkv + (size_t)(base + r) * (3 * DIMC) + head * HEADC) + kp;
            float2 q = qp[0];
            float2 k = qp[DIMC / 2];              // +DIMC floats
            Qs[kp][r] = split_bf16_pair(q.x * SCALEC, q.y * SCALEC);
            Ks[kp][r] = split_bf16_pair(k.x, k.y);
        } else {
            Qs[kp][r] = make_uint2(0u, 0u);
            Ks[kp][r] = make_uint2(0u, 0u);
        }
    }
    // ---- stage V: [mpair][col d], pairing along keys m ----
    for (int idx = tid; idx < 32 * 32; idx += 64) {
        int mp = idx >> 5, d = idx & 31;
        if (2 * mp + 1 < NNC) {                    // 54/2 = 27 full pairs
            const float* vp = qkv + (size_t)(base + 2 * mp) * (3 * DIMC) + 2 * DIMC + head * HEADC + d;
            Vs[mp][d] = split_bf16_pair(vp[0], vp[3 * DIMC]);
        } else {
            Vs[mp][d] = make_uint2(0u, 0u);
        }
    }
    for (int i = tid; i < 169; i += 64) bt[i] = rpb[i * NHC + head];
    if (tid < 49) fidx_s[tid] = (unsigned char)((tid / 7) * 13 + (tid % 7));
    if (tid < NNC) {
        int i = tid;
        if (i < PC) regn_s[i] = -1;
        else {
            int p = i - PC;
            int r = p / 7, c = p % 7;
            int w = bw & 63;
            int gh = (w >> 3) * 7 + r;
            int gw = (w & 7) * 7 + c;
            int rh = gh < 49 ? 0 : (gh < 53 ? 1 : 2);
            int rw = gw < 49 ? 0 : (gw < 53 ? 1 : 2);
            regn_s[i] = rh * 3 + rw;
        }
    }
    __syncthreads();

    // ---- S = Q @ K^T (64x64x32), warp wid covers n-tiles [wid*4, wid*4+4) ----
    #pragma unroll
    for (int mi = 0; mi < 4; mi++) {
        const int m = mi * 16 + gid;
        #pragma unroll
        for (int nj = 0; nj < 4; nj++) {
            const int ni = wid * 4 + nj;
            const int n  = ni * 8 + gid;
            float c[4] = {0.f, 0.f, 0.f, 0.f};
            #pragma unroll
            for (int ks = 0; ks < 2; ks++) {
                const int kb = ks * 8;
                uint2 a0 = Qs[kb + tig    ][m];
                uint2 a1 = Qs[kb + tig    ][m + 8];
                uint2 a2 = Qs[kb + tig + 4][m];
                uint2 a3 = Qs[kb + tig + 4][m + 8];
                uint2 b0 = Ks[kb + tig    ][n];
                uint2 b1 = Ks[kb + tig + 4][n];
                mma16(c, a0.x, a1.x, a2.x, a3.x, b0.x, b1.x);   // hi*hi
                mma16(c, a0.x, a1.x, a2.x, a3.x, b0.y, b1.y);   // hi*lo
                mma16(c, a0.y, a1.y, a2.y, a3.y, b0.x, b1.x);   // lo*hi
            }
            const int col = ni * 8 + 2 * tig;
            Ss[m    ][col]     = c[0];
            Ss[m    ][col + 1] = c[1];
            Ss[m + 8][col]     = c[2];
            Ss[m + 8][col + 1] = c[3];
        }
    }
    __syncthreads();

    // ---- scalar softmax over keys; writes P split pairs (aliases Q/K) ----
    const int t = tid;
    if (t < NNC) {
        const bool feat = (t >= PC);
        int tb = 0;
        unsigned mlo = 0, mhi = 0;
        if (feat) {
            int p = t - PC;
            tb = (p / 7 + 6) * 13 + (p % 7 + 6);
            int myreg = regn_s[t];
            #pragma unroll 7
            for (int m = PC; m < NNC; m++) {
                if (regn_s[m] != myreg) {
                    if (m < 32) mlo |= 1u << m;
                    else        mhi |= 1u << (m - 32);
                }
            }
        }
        float mx = -1e30f;
        #pragma unroll 6
        for (int m = 0; m < NNC; m++) {
            float a = Ss[t][m];
            if (feat && m >= PC) {
                int idx = tb - (int)fidx_s[m - PC];
                float badd = bt[idx];
                bool msk = (m < 32) ? ((mlo >> m) & 1u) : ((mhi >> (m - 32)) & 1u);
                a += msk ? (badd - 100.f) : badd;
            }
            Ss[t][m] = a;
            mx = fmaxf(mx, a);
        }
        float sum = 0.f;
        #pragma unroll 6
        for (int m = 0; m < NNC; m++) {
            float e = __expf(Ss[t][m] - mx);
            sum += e;
            Ss[t][m] = e;
        }
        const float inv = 1.0f / sum;
        #pragma unroll
        for (int mp = 0; mp < 27; mp++)
            Ps[mp][t] = split_bf16_pair(Ss[t][2 * mp] * inv, Ss[t][2 * mp + 1] * inv);
        #pragma unroll
        for (int mp = 27; mp < 32; mp++) Ps[mp][t] = make_uint2(0u, 0u);
    } else {
        // pad rows of P (A-operand rows 54..63) -> zero so MMA reads are benign
        #pragma unroll
        for (int mp = 0; mp < 32; mp++) Ps[mp][t] = make_uint2(0u, 0u);
    }
    __syncthreads();

    // ---- O = P @ V (64x32x64), warp wid covers n-tiles [wid*2, wid*2+2) ----
    #pragma unroll
    for (int mi = 0; mi < 4; mi++) {
        const int m = mi * 16 + gid;
        #pragma unroll
        for (int nj = 0; nj < 2; nj++) {
            const int ni = wid * 2 + nj;
            const int n  = ni * 8 + gid;
            float c[4] = {0.f, 0.f, 0.f, 0.f};
            #pragma unroll
            for (int ks = 0; ks < 4; ks++) {
                const int kb = ks * 8;
                uint2 a0 = Ps[kb + tig    ][m];
                uint2 a1 = Ps[kb + tig    ][m + 8];
                uint2 a2 = Ps[kb + tig + 4][m];
                uint2 a3 = Ps[kb + tig + 4][m + 8];
                uint2 b0 = Vs[kb + tig    ][n];
                uint2 b1 = Vs[kb + tig + 4][n];
                mma16(c, a0.x, a1.x, a2.x, a3.x, b0.x, b1.x);   // hi*hi
                mma16(c, a0.x, a1.x, a2.x, a3.x, b0.y, b1.y);   // hi*lo
                mma16(c, a0.y, a1.y, a2.y, a3.y, b0.x, b1.x);   // lo*hi
            }
            const int r0 = mi * 16 + gid, r1 = r0 + 8;
            const int opi = head * 16 + ni * 4 + tig;
            if (r0 < NNC)
                g_attno_sp[(size_t)(base + r0) * 48 + opi] = split_bf16_pair(c[0], c[1]);
            if (r1 < NNC)
                g_attno_sp[(size_t)(base + r1) * 48 + opi] = split_bf16_pair(c[2], c[3]);
        }
    }
}

// ---------------- launch ----------------
extern "C" void kernel_launch(void* const* d_in, const int* in_sizes, int n_in,
                              void* d_out, int out_size) {
    const float* x       = (const float*)d_in[0];
    const float* norm1_g = (const float*)d_in[1];
    const float* norm1_b = (const float*)d_in[2];
    const float* qkv_w   = (const float*)d_in[3];
    const float* qkv_b   = (const float*)d_in[4];
    const float* rpb     = (const float*)d_in[5];
    const float* proj_w  = (const float*)d_in[6];
    const float* proj_b  = (const float*)d_in[7];
    const float* norm2_g = (const float*)d_in[8];
    const float* norm2_b = (const float*)d_in[9];
    const float* fc1_w   = (const float*)d_in[10];
    const float* fc1_b   = (const float*)d_in[11];
    const float* fc2_w   = (const float*)d_in[12];
    const float* fc2_b   = (const float*)d_in[13];
    float* out = (float*)d_out;

    uint2 *p_xw, *p_attno, *p_yn, *p_h, *p_wq, *p_wp, *p_w1, *p_w2;
    float *p_qkv, *p_y;
    cudaGetSymbolAddress((void**)&p_xw,    g_xw_sp);
    cudaGetSymbolAddress((void**)&p_qkv,   g_qkv);
    cudaGetSymbolAddress((void**)&p_attno, g_attno_sp);
    cudaGetSymbolAddress((void**)&p_y,     g_y);
    cudaGetSymbolAddress((void**)&p_yn,    g_yn_sp);
    cudaGetSymbolAddress((void**)&p_h,     g_h_sp);
    cudaGetSymbolAddress((void**)&p_wq,    g_wq_sp);
    cudaGetSymbolAddress((void**)&p_wp,    g_wp_sp);
    cudaGetSymbolAddress((void**)&p_w1,    g_w1_sp);
    cudaGetSymbolAddress((void**)&p_w2,    g_w2_sp);

    cudaFuncSetAttribute(gemm_tc<0>, cudaFuncAttributeMaxDynamicSharedMemorySize, GEMM_SMEM);
    cudaFuncSetAttribute(gemm_tc<1>, cudaFuncAttributeMaxDynamicSharedMemorySize, GEMM_SMEM);
    cudaFuncSetAttribute(gemm_tc<2>, cudaFuncAttributeMaxDynamicSharedMemorySize, GEMM_SMEM);
    cudaFuncSetAttribute(gemm_tc<3>, cudaFuncAttributeMaxDynamicSharedMemorySize, GEMM_SMEM);

    const int lnBlocks = (MROWS * 32 + 255) / 256;
    const int MB = MROWS / 128;   // 1728

    // 0. pre-split weights
    split_w_kernel<<<216, 256>>>(qkv_w, proj_w, fc1_w, fc2_w);
    // 1. LN1 + window gather (split out)
    ln_gather_kernel<<<lnBlocks, 256>>>(x, norm1_g, norm1_b);
    // 2. QKV GEMM  (N=288, K=96) -> float
    gemm_tc<0><<<dim3(3, MB), 256, GEMM_SMEM>>>(p_xw, p_wq, qkv_b, nullptr, p_qkv, nullptr, 288, 96);
    // 3. MMA windowed attention (split out), one block per (window, head)
    attn_kernel<<<dim3(BATCHC * NWC, NHC), 64>>>(p_qkv, rpb);
    // 4. proj GEMM + scatter + residual-1  (N=96, K=96) -> float y
    gemm_tc<1><<<dim3(1, MB), 256, GEMM_SMEM>>>(p_attno, p_wp, proj_b, x, p_y, nullptr, 96, 96);
    // 5. LN2 (split out)
    ln_plain_kernel<<<lnBlocks, 256>>>(p_y, norm2_g, norm2_b);
    // 6. fc1 + GELU  (N=384, K=96) -> split h
    gemm_tc<2><<<dim3(4, MB), 256, GEMM_SMEM>>>(p_yn, p_w1, fc1_b, nullptr, nullptr, p_h, 384, 96);
    // 7. fc2 + residual-2 -> d_out  (N=96, K=384)
    gemm_tc<3><<<dim3(1, MB), 256, GEMM_SMEM>>>(p_h, p_w2, fc2_b, p_y, out, nullptr, 96, 384);
}

// round 9
// speedup vs baseline: 1.1796x; 1.1796x over previous
#include <cuda_runtime.h>
#include <cuda_bf16.h>
#include <math.h>

// ---------------- problem constants ----------------
#define DIMC    96
#define NHC     3
#define HEADC   32
#define WSC     7
#define SHIFTC  3
#define PC      5
#define HC      56
#define NWC     64
#define TPC     320
#define NNC     54
#define BATCHC  64
#define TOKC    3456
#define MROWS   (BATCHC * NWC * NNC)   // 221184
#define HIDC    384
#define SCALEC  0.17677669529663687f

// ---------------- scratch (split format: uint2{hi bf16 pair, lo bf16 pair}) ----------------
__device__ __align__(16) uint2 g_xw_sp   [MROWS * 48];            // LN1 out, window order
__device__ float               g_qkv     [(size_t)MROWS * 3 * DIMC];
__device__ __align__(16) uint2 g_attno_sp[MROWS * 48];            // attn out, window order
__device__ float               g_y       [MROWS * DIMC];          // residual stream (fp32)
__device__ __align__(16) uint2 g_yn_sp   [MROWS * 48];            // LN2 out
__device__ __align__(16) uint2 g_h_sp    [(size_t)MROWS * 192];   // fc1+GELU out
// pre-split weights [kpair][n]
__device__ __align__(16) uint2 g_wq_sp[48 * 288];
__device__ __align__(16) uint2 g_wp_sp[48 * 96];
__device__ __align__(16) uint2 g_w1_sp[48 * 384];
__device__ __align__(16) uint2 g_w2_sp[192 * 96];

__device__ __forceinline__ int map_token(int bw, int n) {
    int b = bw >> 6;
    int w = bw & 63;
    int tok;
    if (n < PC) {
        tok = w * PC + n;
    } else {
        int p  = n - PC;
        int r  = p / 7, c = p % 7;
        int wh = w >> 3, ww = w & 7;
        int hr = wh * 7 + r + SHIFTC; if (hr >= HC) hr -= HC;
        int wc = ww * 7 + c + SHIFTC; if (wc >= HC) wc -= HC;
        tok = TPC + hr * HC + wc;
    }
    return b * TOKC + tok;
}

__device__ __forceinline__ float warp_sum(float v) {
    #pragma unroll
    for (int o = 16; o; o >>= 1) v += __shfl_xor_sync(0xffffffffu, v, o);
    return v;
}

__device__ __forceinline__ uint2 split_bf16_pair(float x0, float x1) {
    __nv_bfloat16 h0 = __float2bfloat16(x0);
    __nv_bfloat16 h1 = __float2bfloat16(x1);
    float r0 = x0 - __bfloat162float(h0);
    float r1 = x1 - __bfloat162float(h1);
    __nv_bfloat16 l0 = __float2bfloat16(r0);
    __nv_bfloat16 l1 = __float2bfloat16(r1);
    uint2 o;
    o.x = ((unsigned)__bfloat16_as_ushort(h1) << 16) | (unsigned)__bfloat16_as_ushort(h0);
    o.y = ((unsigned)__bfloat16_as_ushort(l1) << 16) | (unsigned)__bfloat16_as_ushort(l0);
    return o;
}

// ---- packed f32x2 helpers (sm_103a; FFMA2 only reachable via PTX) ----
__device__ __forceinline__ unsigned long long pack2(float lo, float hi) {
    unsigned long long d;
    asm("mov.b64 %0, {%1, %2};" : "=l"(d) : "f"(lo), "f"(hi));
    return d;
}
__device__ __forceinline__ void unpack2(float& lo, float& hi, unsigned long long v) {
    asm("mov.b64 {%0, %1}, %2;" : "=f"(lo), "=f"(hi) : "l"(v));
}
__device__ __forceinline__ unsigned long long fma2(unsigned long long a, unsigned long long b,
                                                   unsigned long long c) {
    unsigned long long d;
    asm("fma.rn.f32x2 %0, %1, %2, %3;" : "=l"(d) : "l"(a), "l"(b), "l"(c));
    return d;
}
__device__ __forceinline__ unsigned long long add2(unsigned long long a, unsigned long long b) {
    unsigned long long d;
    asm("add.rn.f32x2 %0, %1, %2;" : "=l"(d) : "l"(a), "l"(b));
    return d;
}
__device__ __forceinline__ unsigned long long mul2(unsigned long long a, unsigned long long b) {
    unsigned long long d;
    asm("mul.rn.f32x2 %0, %1, %2;" : "=l"(d) : "l"(a), "l"(b));
    return d;
}

// ---------------- weight pre-split ----------------
__global__ __launch_bounds__(256)
void split_w_kernel(const float* __restrict__ qkv_w, const float* __restrict__ proj_w,
                    const float* __restrict__ fc1_w, const float* __restrict__ fc2_w) {
    int i = blockIdx.x * blockDim.x + threadIdx.x;
    if (i < 13824) {
        int kp = i / 288, n = i % 288;
        g_wq_sp[i] = split_bf16_pair(qkv_w[(2 * kp) * 288 + n], qkv_w[(2 * kp + 1) * 288 + n]);
    } else if (i < 18432) {
        int j = i - 13824, kp = j / 96, n = j % 96;
        g_wp_sp[j] = split_bf16_pair(proj_w[(2 * kp) * 96 + n], proj_w[(2 * kp + 1) * 96 + n]);
    } else if (i < 36864) {
        int j = i - 18432, kp = j / 384, n = j % 384;
        g_w1_sp[j] = split_bf16_pair(fc1_w[(2 * kp) * 384 + n], fc1_w[(2 * kp + 1) * 384 + n]);
    } else if (i < 55296) {
        int j = i - 36864, kp = j / 96, n = j % 96;
        g_w2_sp[j] = split_bf16_pair(fc2_w[(2 * kp) * 96 + n], fc2_w[(2 * kp + 1) * 96 + n]);
    }
}

// ---------------- LN kernels (write split pairs) ----------------
__global__ __launch_bounds__(256)
void ln_gather_kernel(const float* __restrict__ x,
                      const float* __restrict__ g, const float* __restrict__ bta) {
    int row  = (blockIdx.x * blockDim.x + threadIdx.x) >> 5;
    int lane = threadIdx.x & 31;
    if (row >= MROWS) return;
    int bw = row / NNC, n = row % NNC;
    const float2* src2 = (const float2*)(x + (size_t)map_token(bw, n) * DIMC);
    float2 a0 = src2[lane];
    float2 a1 = make_float2(0.f, 0.f);
    if (lane < 16) a1 = src2[32 + lane];
    float s = a0.x + a0.y + a1.x + a1.y;
    float mean = warp_sum(s) * (1.f / 96.f);
    float d0x = a0.x - mean, d0y = a0.y - mean;
    float d1x = a1.x - mean, d1y = a1.y - mean;
    float vq = d0x * d0x + d0y * d0y + (lane < 16 ? d1x * d1x + d1y * d1y : 0.f);
    float var = warp_sum(vq) * (1.f / 96.f);
    float inv = rsqrtf(var + 1e-5f);
    const float2* g2 = (const float2*)g;
    const float2* b2 = (const float2*)bta;
    uint2* dst = g_xw_sp + (size_t)row * 48;
    float2 G = g2[lane], B = b2[lane];
    dst[lane] = split_bf16_pair(d0x * inv * G.x + B.x, d0y * inv * G.y + B.y);
    if (lane < 16) {
        float2 G1 = g2[32 + lane], B1 = b2[32 + lane];
        dst[32 + lane] = split_bf16_pair(d1x * inv * G1.x + B1.x, d1y * inv * G1.y + B1.y);
    }
}

__global__ __launch_bounds__(256)
void ln_plain_kernel(const float* __restrict__ y,
                     const float* __restrict__ g, const float* __restrict__ bta) {
    int row  = (blockIdx.x * blockDim.x + threadIdx.x) >> 5;
    int lane = threadIdx.x & 31;
    if (row >= MROWS) return;
    const float2* src2 = (const float2*)(y + (size_t)row * DIMC);
    float2 a0 = src2[lane];
    float2 a1 = make_float2(0.f, 0.f);
    if (lane < 16) a1 = src2[32 + lane];
    float s = a0.x + a0.y + a1.x + a1.y;
    float mean = warp_sum(s) * (1.f / 96.f);
    float d0x = a0.x - mean, d0y = a0.y - mean;
    float d1x = a1.x - mean, d1y = a1.y - mean;
    float vq = d0x * d0x + d0y * d0y + (lane < 16 ? d1x * d1x + d1y * d1y : 0.f);
    float var = warp_sum(vq) * (1.f / 96.f);
    float inv = rsqrtf(var + 1e-5f);
    const float2* g2 = (const float2*)g;
    const float2* b2 = (const float2*)bta;
    uint2* dst = g_yn_sp + (size_t)row * 48;
    float2 G = g2[lane], B = b2[lane];
    dst[lane] = split_bf16_pair(d0x * inv * G.x + B.x, d0y * inv * G.y + B.y);
    if (lane < 16) {
        float2 G1 = g2[32 + lane], B1 = b2[32 + lane];
        dst[32 + lane] = split_bf16_pair(d1x * inv * G1.x + B1.x, d1y * inv * G1.y + B1.y);
    }
}

// ---------------- BF16x3 tensor-core GEMM (unchanged) ----------------
__device__ __forceinline__ void mma16(float c[4],
                                      unsigned a0, unsigned a1, unsigned a2, unsigned a3,
                                      unsigned b0, unsigned b1) {
    asm volatile("mma.sync.aligned.m16n8k16.row.col.f32.bf16.bf16.f32 "
                 "{%0,%1,%2,%3}, {%4,%5,%6,%7}, {%8,%9}, {%0,%1,%2,%3};\n"
                 : "+f"(c[0]), "+f"(c[1]), "+f"(c[2]), "+f"(c[3])
                 : "r"(a0), "r"(a1), "r"(a2), "r"(a3), "r"(b0), "r"(b1));
}

#define GEMM_SMEM ((2 * 16 * 132 + 2 * 16 * 100) * 8)   // 59392 bytes

template<int MODE>
__global__ __launch_bounds__(256, 2)
void gemm_tc(const uint2* __restrict__ A, const uint2* __restrict__ Bw,
             const float* __restrict__ bias, const float* __restrict__ res,
             float* __restrict__ out, uint2* __restrict__ outp, int N, int K) {
    extern __shared__ uint2 smemu[];
    uint2 (*As2)[16][132] = reinterpret_cast<uint2(*)[16][132]>(smemu);
    uint2 (*Bs2)[16][100] = reinterpret_cast<uint2(*)[16][100]>(smemu + 2 * 16 * 132);

    const int tid  = threadIdx.x;
    const int wid  = tid >> 5, lane = tid & 31;
    const int gid  = lane >> 2, tig = lane & 3;
    const int wm   = (wid >> 1) * 32;
    const int wn   = (wid & 1) * 48;
    const int m0   = blockIdx.y * 128;
    const int n0   = blockIdx.x * 96;
    const int KP   = K >> 1;

    int arow[4], akp[4];
    const uint2* aPtr[4];
    #pragma unroll
    for (int j = 0; j < 4; j++) {
        int c = tid + 256 * j;
        arow[j] = c >> 3;
        akp[j]  = (c & 7) * 2;
        aPtr[j] = A + (size_t)(m0 + arow[j]) * KP + akp[j];
    }
    int bkp[3], bn2[3];
    const uint2* bPtr[3];
    #pragma unroll
    for (int j = 0; j < 3; j++) {
        int c = tid + 256 * j;
        bkp[j] = c / 48;
        bn2[j] = (c % 48) * 2;
        bPtr[j] = Bw + (size_t)bkp[j] * N + n0 + bn2[j];
    }

    float acc[2][6][4];
    #pragma unroll
    for (int i = 0; i < 2; i++)
        #pragma unroll
        for (int j = 0; j < 6; j++)
            #pragma unroll
            for (int r = 0; r < 4; r++) acc[i][j][r] = 0.f;

    uint4 aR[4], bR[3];
    #pragma unroll
    for (int j = 0; j < 4; j++) aR[j] = *(const uint4*)(aPtr[j]);
    #pragma unroll
    for (int j = 0; j < 3; j++) bR[j] = *(const uint4*)(bPtr[j]);

    #pragma unroll
    for (int j = 0; j < 4; j++) {
        As2[0][akp[j]][arow[j]]     = make_uint2(aR[j].x, aR[j].y);
        As2[0][akp[j] + 1][arow[j]] = make_uint2(aR[j].z, aR[j].w);
    }
    #pragma unroll
    for (int j = 0; j < 3; j++)
        *(uint4*)&Bs2[0][bkp[j]][bn2[j]] = bR[j];
    __syncthreads();

    const int T = K >> 5;
    for (int t = 0; t < T; t++) {
        const int s = t & 1;
        if (t + 1 < T) {
            const int kt = 16 * (t + 1);
            #pragma unroll
            for (int j = 0; j < 4; j++) aR[j] = *(const uint4*)(aPtr[j] + kt);
            #pragma unroll
            for (int j = 0; j < 3; j++) bR[j] = *(const uint4*)(bPtr[j] + (size_t)kt * N);
        }

        #pragma unroll
        for (int ks = 0; ks < 2; ks++) {
            const int kb = ks * 8;
            uint2 af[2][4];
            #pragma unroll
            for (int mt = 0; mt < 2; mt++) {
                const int m = wm + mt * 16 + gid;
                af[mt][0] = As2[s][kb + tig    ][m];
                af[mt][1] = As2[s][kb + tig    ][m + 8];
                af[mt][2] = As2[s][kb + tig + 4][m];
                af[mt][3] = As2[s][kb + tig + 4][m + 8];
            }
            uint2 bf[6][2];
            #pragma unroll
            for (int nt = 0; nt < 6; nt++) {
                const int n = wn + nt * 8 + gid;
                bf[nt][0] = Bs2[s][kb + tig    ][n];
                bf[nt][1] = Bs2[s][kb + tig + 4][n];
            }
            #pragma unroll
            for (int mt = 0; mt < 2; mt++)
                #pragma unroll
                for (int nt = 0; nt < 6; nt++) {
                    float* c = acc[mt][nt];
                    mma16(c, af[mt][0].x, af[mt][1].x, af[mt][2].x, af[mt][3].x,
                             bf[nt][0].x, bf[nt][1].x);
                    mma16(c, af[mt][0].x, af[mt][1].x, af[mt][2].x, af[mt][3].x,
                             bf[nt][0].y, bf[nt][1].y);
                    mma16(c, af[mt][0].y, af[mt][1].y, af[mt][2].y, af[mt][3].y,
                             bf[nt][0].x, bf[nt][1].x);
                }
        }

        if (t + 1 < T) {
            const int sn = (t + 1) & 1;
            #pragma unroll
            for (int j = 0; j < 4; j++) {
                As2[sn][akp[j]][arow[j]]     = make_uint2(aR[j].x, aR[j].y);
                As2[sn][akp[j] + 1][arow[j]] = make_uint2(aR[j].z, aR[j].w);
            }
            #pragma unroll
            for (int j = 0; j < 3; j++)
                *(uint4*)&Bs2[sn][bkp[j]][bn2[j]] = bR[j];
        }
        __syncthreads();
    }

    float bb[6][2];
    #pragma unroll
    for (int nt = 0; nt < 6; nt++) {
        int c = n0 + wn + nt * 8 + tig * 2;
        bb[nt][0] = bias[c];
        bb[nt][1] = bias[c + 1];
    }

    #pragma unroll
    for (int mt = 0; mt < 2; mt++) {
        #pragma unroll
        for (int half = 0; half < 2; half++) {
            int r = m0 + wm + mt * 16 + gid + half * 8;
            size_t orow;
            if (MODE == 1) orow = (size_t)map_token(r / NNC, r % NNC);
            else           orow = (size_t)r;
            #pragma unroll
            for (int nt = 0; nt < 6; nt++) {
                float v0 = acc[mt][nt][half * 2 + 0] + bb[nt][0];
                float v1 = acc[mt][nt][half * 2 + 1] + bb[nt][1];
                if (MODE == 2) {
                    v0 = 0.5f * v0 * (1.0f + erff(v0 * 0.70710678118654752f));
                    v1 = 0.5f * v1 * (1.0f + erff(v1 * 0.70710678118654752f));
                    uint2* op2 = outp + orow * (size_t)(N >> 1) + ((n0 + wn) >> 1) + tig;
                    op2[nt * 4] = split_bf16_pair(v0, v1);
                } else {
                    float* op = out + orow * N + n0 + wn + tig * 2 + nt * 8;
                    if (MODE == 1 || MODE == 3) {
                        const float* rp = res + orow * N + n0 + wn + tig * 2 + nt * 8;
                        v0 += rp[0];
                        v1 += rp[1];
                    }
                    *(float2*)op = make_float2(v0, v1);
                }
            }
        }
    }
}

// ---------------- windowed attention: scalar 3-phase, packed f32x2 math ----------------
// One block per (window, head), 64 threads. Structure identical to the R6
// passing kernel; QK and PV inner loops use fma.rn.f32x2 (2 lanes/inst).
__global__ __launch_bounds__(64, 8)
void attn_kernel(const float* __restrict__ qkv, const float* __restrict__ rpb) {
    __shared__ float ks[NNC * HEADC];        // 6912 B
    __shared__ float vs[NNC * HEADC];        // 6912 B
    __shared__ float probs[NNC * NNC];       // [m][t]  11664 B
    __shared__ float bt[169];
    __shared__ unsigned char fidx_s[49];
    __shared__ int regn_s[NNC];

    const int bw   = blockIdx.x;
    const int head = blockIdx.y;
    const int base = bw * NNC;
    const int tid  = threadIdx.x;

    for (int idx = tid; idx < NNC * HEADC; idx += 64) {
        int m = idx >> 5, d = idx & 31;
        const float* p = qkv + (size_t)(base + m) * (3 * DIMC) + head * HEADC + d;
        ks[idx] = p[DIMC];
        vs[idx] = p[2 * DIMC];
    }
    for (int i = tid; i < 169; i += 64) bt[i] = rpb[i * NHC + head];
    if (tid < 49) fidx_s[tid] = (unsigned char)((tid / 7) * 13 + (tid % 7));
    if (tid < NNC) {
        int i = tid;
        if (i < PC) regn_s[i] = -1;
        else {
            int p = i - PC;
            int r = p / 7, c = p % 7;
            int w = bw & 63;
            int gh = (w >> 3) * 7 + r;
            int gw = (w & 7) * 7 + c;
            int rh = gh < 49 ? 0 : (gh < 53 ? 1 : 2);
            int rw = gw < 49 ? 0 : (gw < 53 ? 1 : 2);
            regn_s[i] = rh * 3 + rw;
        }
    }
    __syncthreads();

    const int t = tid;
    if (t >= NNC) return;

    // Q row (scaled), packed into 16 f32x2 lanes
    const ulonglong2* qp2 = (const ulonglong2*)(qkv + (size_t)(base + t) * (3 * DIMC) + head * HEADC);
    const unsigned long long sc2 = pack2(SCALEC, SCALEC);
    unsigned long long q2[16];
    #pragma unroll
    for (int j = 0; j < 8; j++) {
        ulonglong2 qq = qp2[j];
        q2[2 * j]     = mul2(qq.x, sc2);
        q2[2 * j + 1] = mul2(qq.y, sc2);
    }

    const bool feat = (t >= PC);
    int tb = 0;
    unsigned mlo = 0, mhi = 0;
    if (feat) {
        int p = t - PC;
        tb = (p / 7 + 6) * 13 + (p % 7 + 6);
        int myreg = regn_s[t];
        #pragma unroll 7
        for (int m = PC; m < NNC; m++) {
            if (regn_s[m] != myreg) {
                if (m < 32) mlo |= 1u << m;
                else        mhi |= 1u << (m - 32);
            }
        }
    }

    // ---- phase A: raw scores -> smem, running max in reg ----
    float mx = -1e30f;
    #pragma unroll 6
    for (int m = 0; m < NNC; m++) {
        const ulonglong2* k2p = (const ulonglong2*)(ks + m * HEADC);
        unsigned long long c0 = 0ull, c1 = 0ull, c2 = 0ull, c3 = 0ull;
        #pragma unroll
        for (int j = 0; j < 8; j += 2) {
            ulonglong2 ka = k2p[j];
            ulonglong2 kb = k2p[j + 1];
            c0 = fma2(q2[2 * j],     ka.x, c0);
            c1 = fma2(q2[2 * j + 1], ka.y, c1);
            c2 = fma2(q2[2 * j + 2], kb.x, c2);
            c3 = fma2(q2[2 * j + 3], kb.y, c3);
        }
        unsigned long long cs = add2(add2(c0, c1), add2(c2, c3));
        float alo, ahi;
        unpack2(alo, ahi, cs);
        float a = alo + ahi;
        if (feat && m >= PC) {
            int idx = tb - (int)fidx_s[m - PC];
            float badd = bt[idx];
            bool msk = (m < 32) ? ((mlo >> m) & 1u) : ((mhi >> (m - 32)) & 1u);
            a += msk ? (badd - 100.f) : badd;
        }
        mx = fmaxf(mx, a);
        probs[m * NNC + t] = a;
    }

    // ---- phase B: exp + sum, write probs back ----
    float sum = 0.f;
    #pragma unroll 6
    for (int m = 0; m < NNC; m++) {
        float e = __expf(probs[m * NNC + t] - mx);
        sum += e;
        probs[m * NNC + t] = e;
    }
    const float inv = 1.0f / sum;

    // ---- phase C: P @ V with packed accumulators ----
    unsigned long long acc2[16];
    #pragma unroll
    for (int j = 0; j < 16; j++) acc2[j] = 0ull;
    #pragma unroll 6
    for (int m = 0; m < NNC; m++) {
        const float pm = probs[m * NNC + t] * inv;
        const unsigned long long pm2 = pack2(pm, pm);
        const ulonglong2* v2p = (const ulonglong2*)(vs + m * HEADC);
        #pragma unroll
        for (int j = 0; j < 8; j++) {
            ulonglong2 vv = v2p[j];
            acc2[2 * j]     = fma2(pm2, vv.x, acc2[2 * j]);
            acc2[2 * j + 1] = fma2(pm2, vv.y, acc2[2 * j + 1]);
        }
    }

    // write split pairs for the proj GEMM
    uint2* op = g_attno_sp + (size_t)(base + t) * 48 + head * 16;
    #pragma unroll
    for (int j = 0; j < 16; j++) {
        float lo, hi;
        unpack2(lo, hi, acc2[j]);
        op[j] = split_bf16_pair(lo, hi);
    }
}

// ---------------- launch ----------------
extern "C" void kernel_launch(void* const* d_in, const int* in_sizes, int n_in,
                              void* d_out, int out_size) {
    const float* x       = (const float*)d_in[0];
    const float* norm1_g = (const float*)d_in[1];
    const float* norm1_b = (const float*)d_in[2];
    const float* qkv_w   = (const float*)d_in[3];
    const float* qkv_b   = (const float*)d_in[4];
    const float* rpb     = (const float*)d_in[5];
    const float* proj_w  = (const float*)d_in[6];
    const float* proj_b  = (const float*)d_in[7];
    const float* norm2_g = (const float*)d_in[8];
    const float* norm2_b = (const float*)d_in[9];
    const float* fc1_w   = (const float*)d_in[10];
    const float* fc1_b   = (const float*)d_in[11];
    const float* fc2_w   = (const float*)d_in[12];
    const float* fc2_b   = (const float*)d_in[13];
    float* out = (float*)d_out;

    uint2 *p_xw, *p_attno, *p_yn, *p_h, *p_wq, *p_wp, *p_w1, *p_w2;
    float *p_qkv, *p_y;
    cudaGetSymbolAddress((void**)&p_xw,    g_xw_sp);
    cudaGetSymbolAddress((void**)&p_qkv,   g_qkv);
    cudaGetSymbolAddress((void**)&p_attno, g_attno_sp);
    cudaGetSymbolAddress((void**)&p_y,     g_y);
    cudaGetSymbolAddress((void**)&p_yn,    g_yn_sp);
    cudaGetSymbolAddress((void**)&p_h,     g_h_sp);
    cudaGetSymbolAddress((void**)&p_wq,    g_wq_sp);
    cudaGetSymbolAddress((void**)&p_wp,    g_wp_sp);
    cudaGetSymbolAddress((void**)&p_w1,    g_w1_sp);
    cudaGetSymbolAddress((void**)&p_w2,    g_w2_sp);

    cudaFuncSetAttribute(gemm_tc<0>, cudaFuncAttributeMaxDynamicSharedMemorySize, GEMM_SMEM);
    cudaFuncSetAttribute(gemm_tc<1>, cudaFuncAttributeMaxDynamicSharedMemorySize, GEMM_SMEM);
    cudaFuncSetAttribute(gemm_tc<2>, cudaFuncAttributeMaxDynamicSharedMemorySize, GEMM_SMEM);
    cudaFuncSetAttribute(gemm_tc<3>, cudaFuncAttributeMaxDynamicSharedMemorySize, GEMM_SMEM);

    const int lnBlocks = (MROWS * 32 + 255) / 256;
    const int MB = MROWS / 128;   // 1728

    // 0. pre-split weights
    split_w_kernel<<<216, 256>>>(qkv_w, proj_w, fc1_w, fc2_w);
    // 1. LN1 + window gather (split out)
    ln_gather_kernel<<<lnBlocks, 256>>>(x, norm1_g, norm1_b);
    // 2. QKV GEMM  (N=288, K=96) -> float
    gemm_tc<0><<<dim3(3, MB), 256, GEMM_SMEM>>>(p_xw, p_wq, qkv_b, nullptr, p_qkv, nullptr, 288, 96);
    // 3. windowed attention (split out), one block per (window, head)
    attn_kernel<<<dim3(BATCHC * NWC, NHC), 64>>>(p_qkv, rpb);
    // 4. proj GEMM + scatter + residual-1  (N=96, K=96) -> float y
    gemm_tc<1><<<dim3(1, MB), 256, GEMM_SMEM>>>(p_attno, p_wp, proj_b, x, p_y, nullptr, 96, 96);
    // 5. LN2 (split out)
    ln_plain_kernel<<<lnBlocks, 256>>>(p_y, norm2_g, norm2_b);
    // 6. fc1 + GELU  (N=384, K=96) -> split h
    gemm_tc<2><<<dim3(4, MB), 256, GEMM_SMEM>>>(p_yn, p_w1, fc1_b, nullptr, nullptr, p_h, 384, 96);
    // 7. fc2 + residual-2 -> d_out  (N=96, K=384)
    gemm_tc<3><<<dim3(1, MB), 256, GEMM_SMEM>>>(p_h, p_w2, fc2_b, p_y, out, nullptr, 96, 384);
}

// round 10
// speedup vs baseline: 1.3324x; 1.1295x over previous
#include <cuda_runtime.h>
#include <cuda_bf16.h>
#include <math.h>

// ---------------- problem constants ----------------
#define DIMC    96
#define NHC     3
#define HEADC   32
#define WSC     7
#define SHIFTC  3
#define PC      5
#define HC      56
#define NWC     64
#define TPC     320
#define NNC     54
#define BATCHC  64
#define TOKC    3456
#define MROWS   (BATCHC * NWC * NNC)   // 221184
#define HIDC    384
#define SCALEC  0.17677669529663687f

// ---------------- scratch (split format: uint2{hi bf16 pair, lo bf16 pair}) ----------------
__device__ __align__(16) uint2 g_xw_sp   [MROWS * 48];            // LN1 out, window order
__device__ float               g_qkv     [(size_t)MROWS * 3 * DIMC];
__device__ __align__(16) uint2 g_attno_sp[MROWS * 48];            // attn out, window order
__device__ float               g_y       [MROWS * DIMC];          // residual stream (fp32)
__device__ __align__(16) uint2 g_yn_sp   [MROWS * 48];            // LN2 out
// pre-split weights [kpair][n]
__device__ __align__(16) uint2 g_wq_sp[48 * 288];
__device__ __align__(16) uint2 g_wp_sp[48 * 96];
__device__ __align__(16) uint2 g_w1_sp[48 * 384];
__device__ __align__(16) uint2 g_w2_sp[192 * 96];

__device__ __forceinline__ int map_token(int bw, int n) {
    int b = bw >> 6;
    int w = bw & 63;
    int tok;
    if (n < PC) {
        tok = w * PC + n;
    } else {
        int p  = n - PC;
        int r  = p / 7, c = p % 7;
        int wh = w >> 3, ww = w & 7;
        int hr = wh * 7 + r + SHIFTC; if (hr >= HC) hr -= HC;
        int wc = ww * 7 + c + SHIFTC; if (wc >= HC) wc -= HC;
        tok = TPC + hr * HC + wc;
    }
    return b * TOKC + tok;
}

__device__ __forceinline__ float warp_sum(float v) {
    #pragma unroll
    for (int o = 16; o; o >>= 1) v += __shfl_xor_sync(0xffffffffu, v, o);
    return v;
}

__device__ __forceinline__ uint2 split_bf16_pair(float x0, float x1) {
    __nv_bfloat16 h0 = __float2bfloat16(x0);
    __nv_bfloat16 h1 = __float2bfloat16(x1);
    float r0 = x0 - __bfloat162float(h0);
    float r1 = x1 - __bfloat162float(h1);
    __nv_bfloat16 l0 = __float2bfloat16(r0);
    __nv_bfloat16 l1 = __float2bfloat16(r1);
    uint2 o;
    o.x = ((unsigned)__bfloat16_as_ushort(h1) << 16) | (unsigned)__bfloat16_as_ushort(h0);
    o.y = ((unsigned)__bfloat16_as_ushort(l1) << 16) | (unsigned)__bfloat16_as_ushort(l0);
    return o;
}

// ---- packed f32x2 helpers ----
__device__ __forceinline__ unsigned long long pack2(float lo, float hi) {
    unsigned long long d;
    asm("mov.b64 %0, {%1, %2};" : "=l"(d) : "f"(lo), "f"(hi));
    return d;
}
__device__ __forceinline__ void unpack2(float& lo, float& hi, unsigned long long v) {
    asm("mov.b64 {%0, %1}, %2;" : "=f"(lo), "=f"(hi) : "l"(v));
}
__device__ __forceinline__ unsigned long long fma2(unsigned long long a, unsigned long long b,
                                                   unsigned long long c) {
    unsigned long long d;
    asm("fma.rn.f32x2 %0, %1, %2, %3;" : "=l"(d) : "l"(a), "l"(b), "l"(c));
    return d;
}
__device__ __forceinline__ unsigned long long add2(unsigned long long a, unsigned long long b) {
    unsigned long long d;
    asm("add.rn.f32x2 %0, %1, %2;" : "=l"(d) : "l"(a), "l"(b));
    return d;
}
__device__ __forceinline__ unsigned long long mul2(unsigned long long a, unsigned long long b) {
    unsigned long long d;
    asm("mul.rn.f32x2 %0, %1, %2;" : "=l"(d) : "l"(a), "l"(b));
    return d;
}

// ---------------- weight pre-split ----------------
__global__ __launch_bounds__(256)
void split_w_kernel(const float* __restrict__ qkv_w, const float* __restrict__ proj_w,
                    const float* __restrict__ fc1_w, const float* __restrict__ fc2_w) {
    int i = blockIdx.x * blockDim.x + threadIdx.x;
    if (i < 13824) {
        int kp = i / 288, n = i % 288;
        g_wq_sp[i] = split_bf16_pair(qkv_w[(2 * kp) * 288 + n], qkv_w[(2 * kp + 1) * 288 + n]);
    } else if (i < 18432) {
        int j = i - 13824, kp = j / 96, n = j % 96;
        g_wp_sp[j] = split_bf16_pair(proj_w[(2 * kp) * 96 + n], proj_w[(2 * kp + 1) * 96 + n]);
    } else if (i < 36864) {
        int j = i - 18432, kp = j / 384, n = j % 384;
        g_w1_sp[j] = split_bf16_pair(fc1_w[(2 * kp) * 384 + n], fc1_w[(2 * kp + 1) * 384 + n]);
    } else if (i < 55296) {
        int j = i - 36864, kp = j / 96, n = j % 96;
        g_w2_sp[j] = split_bf16_pair(fc2_w[(2 * kp) * 96 + n], fc2_w[(2 * kp + 1) * 96 + n]);
    }
}

// ---------------- LN kernels (write split pairs) ----------------
__global__ __launch_bounds__(256)
void ln_gather_kernel(const float* __restrict__ x,
                      const float* __restrict__ g, const float* __restrict__ bta) {
    int row  = (blockIdx.x * blockDim.x + threadIdx.x) >> 5;
    int lane = threadIdx.x & 31;
    if (row >= MROWS) return;
    int bw = row / NNC, n = row % NNC;
    const float2* src2 = (const float2*)(x + (size_t)map_token(bw, n) * DIMC);
    float2 a0 = src2[lane];
    float2 a1 = make_float2(0.f, 0.f);
    if (lane < 16) a1 = src2[32 + lane];
    float s = a0.x + a0.y + a1.x + a1.y;
    float mean = warp_sum(s) * (1.f / 96.f);
    float d0x = a0.x - mean, d0y = a0.y - mean;
    float d1x = a1.x - mean, d1y = a1.y - mean;
    float vq = d0x * d0x + d0y * d0y + (lane < 16 ? d1x * d1x + d1y * d1y : 0.f);
    float var = warp_sum(vq) * (1.f / 96.f);
    float inv = rsqrtf(var + 1e-5f);
    const float2* g2 = (const float2*)g;
    const float2* b2 = (const float2*)bta;
    uint2* dst = g_xw_sp + (size_t)row * 48;
    float2 G = g2[lane], B = b2[lane];
    dst[lane] = split_bf16_pair(d0x * inv * G.x + B.x, d0y * inv * G.y + B.y);
    if (lane < 16) {
        float2 G1 = g2[32 + lane], B1 = b2[32 + lane];
        dst[32 + lane] = split_bf16_pair(d1x * inv * G1.x + B1.x, d1y * inv * G1.y + B1.y);
    }
}

__global__ __launch_bounds__(256)
void ln_plain_kernel(const float* __restrict__ y,
                     const float* __restrict__ g, const float* __restrict__ bta) {
    int row  = (blockIdx.x * blockDim.x + threadIdx.x) >> 5;
    int lane = threadIdx.x & 31;
    if (row >= MROWS) return;
    const float2* src2 = (const float2*)(y + (size_t)row * DIMC);
    float2 a0 = src2[lane];
    float2 a1 = make_float2(0.f, 0.f);
    if (lane < 16) a1 = src2[32 + lane];
    float s = a0.x + a0.y + a1.x + a1.y;
    float mean = warp_sum(s) * (1.f / 96.f);
    float d0x = a0.x - mean, d0y = a0.y - mean;
    float d1x = a1.x - mean, d1y = a1.y - mean;
    float vq = d0x * d0x + d0y * d0y + (lane < 16 ? d1x * d1x + d1y * d1y : 0.f);
    float var = warp_sum(vq) * (1.f / 96.f);
    float inv = rsqrtf(var + 1e-5f);
    const float2* g2 = (const float2*)g;
    const float2* b2 = (const float2*)bta;
    uint2* dst = g_yn_sp + (size_t)row * 48;
    float2 G = g2[lane], B = b2[lane];
    dst[lane] = split_bf16_pair(d0x * inv * G.x + B.x, d0y * inv * G.y + B.y);
    if (lane < 16) {
        float2 G1 = g2[32 + lane], B1 = b2[32 + lane];
        dst[32 + lane] = split_bf16_pair(d1x * inv * G1.x + B1.x, d1y * inv * G1.y + B1.y);
    }
}

// ---------------- BF16x3 tensor-core GEMM (QKV / proj) ----------------
__device__ __forceinline__ void mma16(float c[4],
                                      unsigned a0, unsigned a1, unsigned a2, unsigned a3,
                                      unsigned b0, unsigned b1) {
    asm volatile("mma.sync.aligned.m16n8k16.row.col.f32.bf16.bf16.f32 "
                 "{%0,%1,%2,%3}, {%4,%5,%6,%7}, {%8,%9}, {%0,%1,%2,%3};\n"
                 : "+f"(c[0]), "+f"(c[1]), "+f"(c[2]), "+f"(c[3])
                 : "r"(a0), "r"(a1), "r"(a2), "r"(a3), "r"(b0), "r"(b1));
}

#define GEMM_SMEM ((2 * 16 * 132 + 2 * 16 * 100) * 8)   // 59392 bytes

template<int MODE>
__global__ __launch_bounds__(256, 2)
void gemm_tc(const uint2* __restrict__ A, const uint2* __restrict__ Bw,
             const float* __restrict__ bias, const float* __restrict__ res,
             float* __restrict__ out, int N, int K) {
    extern __shared__ uint2 smemu[];
    uint2 (*As2)[16][132] = reinterpret_cast<uint2(*)[16][132]>(smemu);
    uint2 (*Bs2)[16][100] = reinterpret_cast<uint2(*)[16][100]>(smemu + 2 * 16 * 132);

    const int tid  = threadIdx.x;
    const int wid  = tid >> 5, lane = tid & 31;
    const int gid  = lane >> 2, tig = lane & 3;
    const int wm   = (wid >> 1) * 32;
    const int wn   = (wid & 1) * 48;
    const int m0   = blockIdx.y * 128;
    const int n0   = blockIdx.x * 96;
    const int KP   = K >> 1;

    int arow[4], akp[4];
    const uint2* aPtr[4];
    #pragma unroll
    for (int j = 0; j < 4; j++) {
        int c = tid + 256 * j;
        arow[j] = c >> 3;
        akp[j]  = (c & 7) * 2;
        aPtr[j] = A + (size_t)(m0 + arow[j]) * KP + akp[j];
    }
    int bkp[3], bn2[3];
    const uint2* bPtr[3];
    #pragma unroll
    for (int j = 0; j < 3; j++) {
        int c = tid + 256 * j;
        bkp[j] = c / 48;
        bn2[j] = (c % 48) * 2;
        bPtr[j] = Bw + (size_t)bkp[j] * N + n0 + bn2[j];
    }

    float acc[2][6][4];
    #pragma unroll
    for (int i = 0; i < 2; i++)
        #pragma unroll
        for (int j = 0; j < 6; j++)
            #pragma unroll
            for (int r = 0; r < 4; r++) acc[i][j][r] = 0.f;

    uint4 aR[4], bR[3];
    #pragma unroll
    for (int j = 0; j < 4; j++) aR[j] = *(const uint4*)(aPtr[j]);
    #pragma unroll
    for (int j = 0; j < 3; j++) bR[j] = *(const uint4*)(bPtr[j]);

    #pragma unroll
    for (int j = 0; j < 4; j++) {
        As2[0][akp[j]][arow[j]]     = make_uint2(aR[j].x, aR[j].y);
        As2[0][akp[j] + 1][arow[j]] = make_uint2(aR[j].z, aR[j].w);
    }
    #pragma unroll
    for (int j = 0; j < 3; j++)
        *(uint4*)&Bs2[0][bkp[j]][bn2[j]] = bR[j];
    __syncthreads();

    const int T = K >> 5;
    for (int t = 0; t < T; t++) {
        const int s = t & 1;
        if (t + 1 < T) {
            const int kt = 16 * (t + 1);
            #pragma unroll
            for (int j = 0; j < 4; j++) aR[j] = *(const uint4*)(aPtr[j] + kt);
            #pragma unroll
            for (int j = 0; j < 3; j++) bR[j] = *(const uint4*)(bPtr[j] + (size_t)kt * N);
        }

        #pragma unroll
        for (int ks = 0; ks < 2; ks++) {
            const int kb = ks * 8;
            uint2 af[2][4];
            #pragma unroll
            for (int mt = 0; mt < 2; mt++) {
                const int m = wm + mt * 16 + gid;
                af[mt][0] = As2[s][kb + tig    ][m];
                af[mt][1] = As2[s][kb + tig    ][m + 8];
                af[mt][2] = As2[s][kb + tig + 4][m];
                af[mt][3] = As2[s][kb + tig + 4][m + 8];
            }
            uint2 bf[6][2];
            #pragma unroll
            for (int nt = 0; nt < 6; nt++) {
                const int n = wn + nt * 8 + gid;
                bf[nt][0] = Bs2[s][kb + tig    ][n];
                bf[nt][1] = Bs2[s][kb + tig + 4][n];
            }
            #pragma unroll
            for (int mt = 0; mt < 2; mt++)
                #pragma unroll
                for (int nt = 0; nt < 6; nt++) {
                    float* c = acc[mt][nt];
                    mma16(c, af[mt][0].x, af[mt][1].x, af[mt][2].x, af[mt][3].x,
                             bf[nt][0].x, bf[nt][1].x);
                    mma16(c, af[mt][0].x, af[mt][1].x, af[mt][2].x, af[mt][3].x,
                             bf[nt][0].y, bf[nt][1].y);
                    mma16(c, af[mt][0].y, af[mt][1].y, af[mt][2].y, af[mt][3].y,
                             bf[nt][0].x, bf[nt][1].x);
                }
        }

        if (t + 1 < T) {
            const int sn = (t + 1) & 1;
            #pragma unroll
            for (int j = 0; j < 4; j++) {
                As2[sn][akp[j]][arow[j]]     = make_uint2(aR[j].x, aR[j].y);
                As2[sn][akp[j] + 1][arow[j]] = make_uint2(aR[j].z, aR[j].w);
            }
            #pragma unroll
            for (int j = 0; j < 3; j++)
                *(uint4*)&Bs2[sn][bkp[j]][bn2[j]] = bR[j];
        }
        __syncthreads();
    }

    float bb[6][2];
    #pragma unroll
    for (int nt = 0; nt < 6; nt++) {
        int c = n0 + wn + nt * 8 + tig * 2;
        bb[nt][0] = bias[c];
        bb[nt][1] = bias[c + 1];
    }

    #pragma unroll
    for (int mt = 0; mt < 2; mt++) {
        #pragma unroll
        for (int half = 0; half < 2; half++) {
            int r = m0 + wm + mt * 16 + gid + half * 8;
            size_t orow;
            if (MODE == 1) orow = (size_t)map_token(r / NNC, r % NNC);
            else           orow = (size_t)r;
            float* op = out + orow * N + n0 + wn + tig * 2;
            #pragma unroll
            for (int nt = 0; nt < 6; nt++) {
                float v0 = acc[mt][nt][half * 2 + 0] + bb[nt][0];
                float v1 = acc[mt][nt][half * 2 + 1] + bb[nt][1];
                if (MODE == 1) {
                    const float* rp = res + orow * N + n0 + wn + tig * 2 + nt * 8;
                    v0 += rp[0];
                    v1 += rp[1];
                }
                *(float2*)(op + nt * 8) = make_float2(v0, v1);
            }
        }
    }
}

// ---------------- fused MLP: out = y + GELU(yn @ W1 + b1) @ W2 + b2 ----------------
// Block = 64 rows x 96 out cols, 256 threads (8 warps, 2M x 4N, warp tile 32x24).
// Loop over 4 hidden chunks of 96: fc1 chunk -> GELU -> split pairs into smem Hs
// ([kpair][row], the MMA A-operand layout) -> fc2 partial accumulate in registers.
// Hidden activations never touch HBM (saves 680 MB round-trip).
#define MLP_ASF  (48 * 68)    // yn tile   (26.1 KB)
#define MLP_BS   (48 * 100)   // W chunk   (38.4 KB)
#define MLP_HS   (48 * 68)    // h chunk   (26.1 KB)
#define MLP_SMEM ((MLP_ASF + MLP_BS + MLP_HS) * 8)   // 90624 bytes

__global__ __launch_bounds__(256, 2)
void fused_mlp_kernel(const uint2* __restrict__ A,      // g_yn_sp [row][48]
                      const uint2* __restrict__ W1,     // [48][384]
                      const float* __restrict__ b1,
                      const uint2* __restrict__ W2,     // [192][96]
                      const float* __restrict__ b2,
                      const float* __restrict__ res,    // g_y
                      float* __restrict__ out) {
    extern __shared__ uint2 smemu[];
    uint2 (*AsF)[68]  = reinterpret_cast<uint2(*)[68]>(smemu);
    uint2 (*Bs)[100]  = reinterpret_cast<uint2(*)[100]>(smemu + MLP_ASF);
    uint2 (*Hs)[68]   = reinterpret_cast<uint2(*)[68]>(smemu + MLP_ASF + MLP_BS);

    const int tid  = threadIdx.x;
    const int wid  = tid >> 5, lane = tid & 31;
    const int gid  = lane >> 2, tig = lane & 3;
    const int wm   = (wid >> 2) * 32;          // 2 warps in M
    const int wn   = (wid & 3) * 24;           // 4 warps in N
    const int m0   = blockIdx.x * 64;

    // ---- stage full A tile (64 rows x 48 kpairs) once ----
    #pragma unroll
    for (int j = 0; j < 6; j++) {
        int c   = tid + 256 * j;               // 0..1535
        int row = c / 24;
        int kpp = (c % 24) * 2;
        uint4 v = *(const uint4*)(A + (size_t)(m0 + row) * 48 + kpp);
        AsF[kpp][row]     = make_uint2(v.x, v.y);
        AsF[kpp + 1][row] = make_uint2(v.z, v.w);
    }

    float acc2[2][3][4];
    #pragma unroll
    for (int i = 0; i < 2; i++)
        #pragma unroll
        for (int j = 0; j < 3; j++)
            #pragma unroll
            for (int r = 0; r < 4; r++) acc2[i][j][r] = 0.f;

    for (int cc = 0; cc < 4; cc++) {
        __syncthreads();   // AsF ready (cc=0) / previous fc2 reads of Bs,Hs done (cc>0)

        // ---- stage W1 chunk (48 kp x 96) into Bs ----
        #pragma unroll
        for (int j = 0; j < 9; j++) {
            int c2 = tid + 256 * j;            // 0..2303
            int kp = c2 / 48;
            int n2 = (c2 % 48) * 2;
            uint4 v = *(const uint4*)(W1 + (size_t)kp * 384 + cc * 96 + n2);
            *(uint4*)&Bs[kp][n2] = v;
        }
        __syncthreads();

        // ---- fc1 chunk GEMM: acc1 = A(64x96) @ W1chunk(96x96) ----
        float acc1[2][3][4];
        #pragma unroll
        for (int i = 0; i < 2; i++)
            #pragma unroll
            for (int j = 0; j < 3; j++)
                #pragma unroll
                for (int r = 0; r < 4; r++) acc1[i][j][r] = 0.f;

        #pragma unroll
        for (int kt = 0; kt < 6; kt++) {       // 6 k-steps of 8 kpairs (=16 k)
            const int kb = kt * 8;
            uint2 af[2][4];
            #pragma unroll
            for (int mt = 0; mt < 2; mt++) {
                const int m = wm + mt * 16 + gid;
                af[mt][0] = AsF[kb + tig    ][m];
                af[mt][1] = AsF[kb + tig    ][m + 8];
                af[mt][2] = AsF[kb + tig + 4][m];
                af[mt][3] = AsF[kb + tig + 4][m + 8];
            }
            uint2 bf[3][2];
            #pragma unroll
            for (int nt = 0; nt < 3; nt++) {
                const int n = wn + nt * 8 + gid;
                bf[nt][0] = Bs[kb + tig    ][n];
                bf[nt][1] = Bs[kb + tig + 4][n];
            }
            #pragma unroll
            for (int mt = 0; mt < 2; mt++)
                #pragma unroll
                for (int nt = 0; nt < 3; nt++) {
                    float* c = acc1[mt][nt];
                    mma16(c, af[mt][0].x, af[mt][1].x, af[mt][2].x, af[mt][3].x,
                             bf[nt][0].x, bf[nt][1].x);
                    mma16(c, af[mt][0].x, af[mt][1].x, af[mt][2].x, af[mt][3].x,
                             bf[nt][0].y, bf[nt][1].y);
                    mma16(c, af[mt][0].y, af[mt][1].y, af[mt][2].y, af[mt][3].y,
                             bf[nt][0].x, bf[nt][1].x);
                }
        }

        // ---- epilogue1: +b1, GELU, split -> Hs[kpair][row] ----
        float bb1[3][2];
        #pragma unroll
        for (int nt = 0; nt < 3; nt++) {
            int c = cc * 96 + wn + nt * 8 + tig * 2;
            bb1[nt][0] = b1[c];
            bb1[nt][1] = b1[c + 1];
        }
        #pragma unroll
        for (int mt = 0; mt < 2; mt++) {
            #pragma unroll
            for (int half = 0; half < 2; half++) {
                int r = wm + mt * 16 + gid + half * 8;   // local row 0..63
                #pragma unroll
                for (int nt = 0; nt < 3; nt++) {
                    float v0 = acc1[mt][nt][half * 2 + 0] + bb1[nt][0];
                    float v1 = acc1[mt][nt][half * 2 + 1] + bb1[nt][1];
                    v0 = 0.5f * v0 * (1.0f + erff(v0 * 0.70710678118654752f));
                    v1 = 0.5f * v1 * (1.0f + erff(v1 * 0.70710678118654752f));
                    int p = (wn >> 1) + nt * 4 + tig;    // kpair within chunk 0..47
                    Hs[p][r] = split_bf16_pair(v0, v1);
                }
            }
        }
        __syncthreads();   // Hs complete; Bs (W1) reads done

        // ---- stage W2 chunk (48 kp x 96) into Bs ----
        #pragma unroll
        for (int j = 0; j < 9; j++) {
            int c2 = tid + 256 * j;
            int kp = c2 / 48;
            int n2 = (c2 % 48) * 2;
            uint4 v = *(const uint4*)(W2 + (size_t)(cc * 48 + kp) * 96 + n2);
            *(uint4*)&Bs[kp][n2] = v;
        }
        __syncthreads();

        // ---- fc2 partial: acc2 += H(64x96) @ W2chunk(96x96) ----
        #pragma unroll
        for (int kt = 0; kt < 6; kt++) {
            const int kb = kt * 8;
            uint2 af[2][4];
            #pragma unroll
            for (int mt = 0; mt < 2; mt++) {
                const int m = wm + mt * 16 + gid;
                af[mt][0] = Hs[kb + tig    ][m];
                af[mt][1] = Hs[kb + tig    ][m + 8];
                af[mt][2] = Hs[kb + tig + 4][m];
                af[mt][3] = Hs[kb + tig + 4][m + 8];
            }
            uint2 bf[3][2];
            #pragma unroll
            for (int nt = 0; nt < 3; nt++) {
                const int n = wn + nt * 8 + gid;
                bf[nt][0] = Bs[kb + tig    ][n];
                bf[nt][1] = Bs[kb + tig + 4][n];
            }
            #pragma unroll
            for (int mt = 0; mt < 2; mt++)
                #pragma unroll
                for (int nt = 0; nt < 3; nt++) {
                    float* c = acc2[mt][nt];
                    mma16(c, af[mt][0].x, af[mt][1].x, af[mt][2].x, af[mt][3].x,
                             bf[nt][0].x, bf[nt][1].x);
                    mma16(c, af[mt][0].x, af[mt][1].x, af[mt][2].x, af[mt][3].x,
                             bf[nt][0].y, bf[nt][1].y);
                    mma16(c, af[mt][0].y, af[mt][1].y, af[mt][2].y, af[mt][3].y,
                             bf[nt][0].x, bf[nt][1].x);
                }
        }
    }

    // ---- final epilogue: +b2, +residual -> out ----
    float bb2[3][2];
    #pragma unroll
    for (int nt = 0; nt < 3; nt++) {
        int c = wn + nt * 8 + tig * 2;
        bb2[nt][0] = b2[c];
        bb2[nt][1] = b2[c + 1];
    }
    #pragma unroll
    for (int mt = 0; mt < 2; mt++) {
        #pragma unroll
        for (int half = 0; half < 2; half++) {
            size_t rg = (size_t)(m0 + wm + mt * 16 + gid + half * 8);
            float*       op = out + rg * 96 + wn + tig * 2;
            const float* rp = res + rg * 96 + wn + tig * 2;
            #pragma unroll
            for (int nt = 0; nt < 3; nt++) {
                float v0 = acc2[mt][nt][half * 2 + 0] + bb2[nt][0] + rp[nt * 8];
                float v1 = acc2[mt][nt][half * 2 + 1] + bb2[nt][1] + rp[nt * 8 + 1];
                *(float2*)(op + nt * 8) = make_float2(v0, v1);
            }
        }
    }
}

// ---------------- windowed attention: scalar 3-phase, packed f32x2 (unchanged) ----------------
__global__ __launch_bounds__(64, 8)
void attn_kernel(const float* __restrict__ qkv, const float* __restrict__ rpb) {
    __shared__ float ks[NNC * HEADC];
    __shared__ float vs[NNC * HEADC];
    __shared__ float probs[NNC * NNC];
    __shared__ float bt[169];
    __shared__ unsigned char fidx_s[49];
    __shared__ int regn_s[NNC];

    const int bw   = blockIdx.x;
    const int head = blockIdx.y;
    const int base = bw * NNC;
    const int tid  = threadIdx.x;

    for (int idx = tid; idx < NNC * HEADC; idx += 64) {
        int m = idx >> 5, d = idx & 31;
        const float* p = qkv + (size_t)(base + m) * (3 * DIMC) + head * HEADC + d;
        ks[idx] = p[DIMC];
        vs[idx] = p[2 * DIMC];
    }
    for (int i = tid; i < 169; i += 64) bt[i] = rpb[i * NHC + head];
    if (tid < 49) fidx_s[tid] = (unsigned char)((tid / 7) * 13 + (tid % 7));
    if (tid < NNC) {
        int i = tid;
        if (i < PC) regn_s[i] = -1;
        else {
            int p = i - PC;
            int r = p / 7, c = p % 7;
            int w = bw & 63;
            int gh = (w >> 3) * 7 + r;
            int gw = (w & 7) * 7 + c;
            int rh = gh < 49 ? 0 : (gh < 53 ? 1 : 2);
            int rw = gw < 49 ? 0 : (gw < 53 ? 1 : 2);
            regn_s[i] = rh * 3 + rw;
        }
    }
    __syncthreads();

    const int t = tid;
    if (t >= NNC) return;

    const ulonglong2* qp2 = (const ulonglong2*)(qkv + (size_t)(base + t) * (3 * DIMC) + head * HEADC);
    const unsigned long long sc2 = pack2(SCALEC, SCALEC);
    unsigned long long q2[16];
    #pragma unroll
    for (int j = 0; j < 8; j++) {
        ulonglong2 qq = qp2[j];
        q2[2 * j]     = mul2(qq.x, sc2);
        q2[2 * j + 1] = mul2(qq.y, sc2);
    }

    const bool feat = (t >= PC);
    int tb = 0;
    unsigned mlo = 0, mhi = 0;
    if (feat) {
        int p = t - PC;
        tb = (p / 7 + 6) * 13 + (p % 7 + 6);
        int myreg = regn_s[t];
        #pragma unroll 7
        for (int m = PC; m < NNC; m++) {
            if (regn_s[m] != myreg) {
                if (m < 32) mlo |= 1u << m;
                else        mhi |= 1u << (m - 32);
            }
        }
    }

    float mx = -1e30f;
    #pragma unroll 6
    for (int m = 0; m < NNC; m++) {
        const ulonglong2* k2p = (const ulonglong2*)(ks + m * HEADC);
        unsigned long long c0 = 0ull, c1 = 0ull, c2 = 0ull, c3 = 0ull;
        #pragma unroll
        for (int j = 0; j < 8; j += 2) {
            ulonglong2 ka = k2p[j];
            ulonglong2 kb = k2p[j + 1];
            c0 = fma2(q2[2 * j],     ka.x, c0);
            c1 = fma2(q2[2 * j + 1], ka.y, c1);
            c2 = fma2(q2[2 * j + 2], kb.x, c2);
            c3 = fma2(q2[2 * j + 3], kb.y, c3);
        }
        unsigned long long cs = add2(add2(c0, c1), add2(c2, c3));
        float alo, ahi;
        unpack2(alo, ahi, cs);
        float a = alo + ahi;
        if (feat && m >= PC) {
            int idx = tb - (int)fidx_s[m - PC];
            float badd = bt[idx];
            bool msk = (m < 32) ? ((mlo >> m) & 1u) : ((mhi >> (m - 32)) & 1u);
            a += msk ? (badd - 100.f) : badd;
        }
        mx = fmaxf(mx, a);
        probs[m * NNC + t] = a;
    }

    float sum = 0.f;
    #pragma unroll 6
    for (int m = 0; m < NNC; m++) {
        float e = __expf(probs[m * NNC + t] - mx);
        sum += e;
        probs[m * NNC + t] = e;
    }
    const float inv = 1.0f / sum;

    unsigned long long acc2[16];
    #pragma unroll
    for (int j = 0; j < 16; j++) acc2[j] = 0ull;
    #pragma unroll 6
    for (int m = 0; m < NNC; m++) {
        const float pm = probs[m * NNC + t] * inv;
        const unsigned long long pm2 = pack2(pm, pm);
        const ulonglong2* v2p = (const ulonglong2*)(vs + m * HEADC);
        #pragma unroll
        for (int j = 0; j < 8; j++) {
            ulonglong2 vv = v2p[j];
            acc2[2 * j]     = fma2(pm2, vv.x, acc2[2 * j]);
            acc2[2 * j + 1] = fma2(pm2, vv.y, acc2[2 * j + 1]);
        }
    }

    uint2* op = g_attno_sp + (size_t)(base + t) * 48 + head * 16;
    #pragma unroll
    for (int j = 0; j < 16; j++) {
        float lo, hi;
        unpack2(lo, hi, acc2[j]);
        op[j] = split_bf16_pair(lo, hi);
    }
}

// ---------------- launch ----------------
extern "C" void kernel_launch(void* const* d_in, const int* in_sizes, int n_in,
                              void* d_out, int out_size) {
    const float* x       = (const float*)d_in[0];
    const float* norm1_g = (const float*)d_in[1];
    const float* norm1_b = (const float*)d_in[2];
    const float* qkv_w   = (const float*)d_in[3];
    const float* qkv_b   = (const float*)d_in[4];
    const float* rpb     = (const float*)d_in[5];
    const float* proj_w  = (const float*)d_in[6];
    const float* proj_b  = (const float*)d_in[7];
    const float* norm2_g = (const float*)d_in[8];
    const float* norm2_b = (const float*)d_in[9];
    const float* fc1_w   = (const float*)d_in[10];
    const float* fc1_b   = (const float*)d_in[11];
    const float* fc2_w   = (const float*)d_in[12];
    const float* fc2_b   = (const float*)d_in[13];
    float* out = (float*)d_out;

    uint2 *p_xw, *p_attno, *p_yn, *p_wq, *p_wp, *p_w1, *p_w2;
    float *p_qkv, *p_y;
    cudaGetSymbolAddress((void**)&p_xw,    g_xw_sp);
    cudaGetSymbolAddress((void**)&p_qkv,   g_qkv);
    cudaGetSymbolAddress((void**)&p_attno, g_attno_sp);
    cudaGetSymbolAddress((void**)&p_y,     g_y);
    cudaGetSymbolAddress((void**)&p_yn,    g_yn_sp);
    cudaGetSymbolAddress((void**)&p_wq,    g_wq_sp);
    cudaGetSymbolAddress((void**)&p_wp,    g_wp_sp);
    cudaGetSymbolAddress((void**)&p_w1,    g_w1_sp);
    cudaGetSymbolAddress((void**)&p_w2,    g_w2_sp);

    cudaFuncSetAttribute(gemm_tc<0>, cudaFuncAttributeMaxDynamicSharedMemorySize, GEMM_SMEM);
    cudaFuncSetAttribute(gemm_tc<1>, cudaFuncAttributeMaxDynamicSharedMemorySize, GEMM_SMEM);
    cudaFuncSetAttribute(fused_mlp_kernel, cudaFuncAttributeMaxDynamicSharedMemorySize, MLP_SMEM);

    const int lnBlocks = (MROWS * 32 + 255) / 256;
    const int MB = MROWS / 128;   // 1728

    // 0. pre-split weights
    split_w_kernel<<<216, 256>>>(qkv_w, proj_w, fc1_w, fc2_w);
    // 1. LN1 + window gather (split out)
    ln_gather_kernel<<<lnBlocks, 256>>>(x, norm1_g, norm1_b);
    // 2. QKV GEMM  (N=288, K=96) -> float
    gemm_tc<0><<<dim3(3, MB), 256, GEMM_SMEM>>>(p_xw, p_wq, qkv_b, nullptr, p_qkv, 288, 96);
    // 3. windowed attention (split out)
    attn_kernel<<<dim3(BATCHC * NWC, NHC), 64>>>(p_qkv, rpb);
    // 4. proj GEMM + scatter + residual-1  (N=96, K=96) -> float y
    gemm_tc<1><<<dim3(1, MB), 256, GEMM_SMEM>>>(p_attno, p_wp, proj_b, x, p_y, 96, 96);
    // 5. LN2 (split out)
    ln_plain_kernel<<<lnBlocks, 256>>>(p_y, norm2_g, norm2_b);
    // 6+7. fused MLP: out = y + GELU(yn @ W1 + b1) @ W2 + b2
    fused_mlp_kernel<<<MROWS / 64, 256, MLP_SMEM>>>(p_yn, p_w1, fc1_b, p_w2, fc2_b, p_y, out);
}